// round 14
// baseline (speedup 1.0000x reference)
#include <cuda_runtime.h>
#include <cstdint>
#include <cstddef>

#define L_  8
#define M_  128
#define K_  32
#define D_  16
#define B_  2048
#define N_  1024   /* L_*M_ */
#define NT_ 8      /* batch tiles of 256 */
#define BT_ 256    /* batch-tile width */
#define TPAD 260   /* smem tile row pad (x4 -> 16B-aligned rows) */

#define XT_OFF   0u
#define TR_OFF   ((unsigned)(D_ * B_))
#define OUT_OFF  ((unsigned)(D_ * B_ + N_ * D_ * B_))

static __device__ float g_scratch[(size_t)D_ * B_ + 2ull * N_ * D_ * B_];
static __device__ int   g_f_tr[NT_ * N_];   // [j*N_+n] traceT row-slice ready
static __device__ int   g_f_out[NT_ * N_];  // [j*N_+n] outT row-slice ready
static __device__ int   g_f_x[NT_];         // xT slice ready

// ---- packed fp32x2 helpers (sm_10x) ---------------------------------------
__device__ __forceinline__ unsigned long long fma2(
    unsigned long long a, unsigned long long b, unsigned long long c)
{
    unsigned long long d;
    asm("fma.rn.f32x2 %0, %1, %2, %3;" : "=l"(d) : "l"(a), "l"(b), "l"(c));
    return d;
}
__device__ __forceinline__ unsigned long long pack2(float lo, float hi)
{
    unsigned long long r;
    asm("mov.b64 %0, {%1, %2};" : "=l"(r) : "f"(lo), "f"(hi));
    return r;
}
__device__ __forceinline__ float2 unpack2(unsigned long long v)
{
    float2 r;
    asm("mov.b64 {%0, %1}, %2;" : "=f"(r.x), "=f"(r.y) : "l"(v));
    return r;
}
__device__ __forceinline__ void flag_release(int* p)
{
    asm volatile("st.release.gpu.s32 [%0], %1;" :: "l"(p), "r"(1) : "memory");
}
__device__ __forceinline__ void flag_wait(const int* p)
{
    int v;
    for (;;) {
        asm volatile("ld.acquire.gpu.s32 %0, [%1];" : "=r"(v) : "l"(p) : "memory");
        if (v) break;
        __nanosleep(64);
    }
}

// ---------------------------------------------------------------------------
// Zero the ready flags (must run before fused kernel each replay).
// ---------------------------------------------------------------------------
__global__ void zero_flags_kernel()
{
    int i = blockIdx.x * 256 + threadIdx.x;
    if (i < N_ * NT_) { g_f_tr[i] = 0; g_f_out[i] = 0; }
    if (i < NT_) g_f_x[i] = 0;
}

// ---------------------------------------------------------------------------
// Transpose one (BT_, D) contiguous slice -> 16 rows of BT_ floats.
// ---------------------------------------------------------------------------
__device__ __forceinline__ void transpose_slice(
    float (*tile)[TPAD], const float* __restrict__ src, float* __restrict__ dst,
    int jb, int t)
{
    const float4* s4 = reinterpret_cast<const float4*>(src);
    #pragma unroll
    for (int i = t; i < (BT_ * D_) / 4; i += 128) {
        float4 v = s4[i];
        int bb = i >> 2;
        int d4 = (i & 3) * 4;
        tile[d4 + 0][bb] = v.x;
        tile[d4 + 1][bb] = v.y;
        tile[d4 + 2][bb] = v.z;
        tile[d4 + 3][bb] = v.w;
    }
    __syncthreads();
    #pragma unroll
    for (int i = t; i < (BT_ * D_) / 4; i += 128) {
        int d = i >> 6;
        int c = (i & 63) * 4;
        *reinterpret_cast<float4*>(&dst[(size_t)d * B_ + jb + c]) =
            *reinterpret_cast<const float4*>(&tile[d][c]);
    }
    __syncthreads();
}

// ---------------------------------------------------------------------------
// ONE kernel, TILE-COLUMN-MAJOR bid order:
//   grid = (M_, L_+1, NT_): x = node m, y = phase z (0 = transpose,
//   1..8 = layer z-1), z = batch tile j.  All phases of tile j are issued
//   before tile j+1 -> producer/consumer proximity -> gather reads hit L2.
// Core: R11 (2 batches/thread, fp32x2 d-pair, 2 flights of 16 gathers).
// ---------------------------------------------------------------------------
__global__ void __launch_bounds__(128, 6) fused_all(
    float* __restrict__ out,
    const float* __restrict__ x,
    const float* __restrict__ trace,
    const int* __restrict__ src_node,
    const int* __restrict__ src_feat,
    const float* __restrict__ W,
    const float* __restrict__ bias)
{
    __shared__ union SM {
        float tile[D_][TPAD];                      // transpose staging
        struct {
            float    sWt[K_ * D_];
            float    sBias[D_];
            unsigned sOff[K_];
        } c;                                       // layer compute
    } sm;

    const int m  = blockIdx.x;
    const int z  = blockIdx.y;                     // phase
    const int j  = blockIdx.z;                     // tile column
    const int t  = threadIdx.x;
    const int jb = j * BT_;

    // ======================= transpose blocks (z == 0) ======================
    if (z == 0) {
        #pragma unroll 1
        for (int i = 0; i < 8; ++i) {
            int n = m * 8 + i;
            transpose_slice(sm.tile,
                            trace + ((size_t)n * B_ + jb) * D_,
                            g_scratch + TR_OFF + (size_t)n * D_ * B_, jb, t);
            if (t == 0) {
                __threadfence();
                flag_release(&g_f_tr[j * N_ + n]);
            }
        }
        if (m == 0) {
            transpose_slice(sm.tile, x + (size_t)jb * D_,
                            g_scratch + XT_OFF, jb, t);
            if (t == 0) {
                __threadfence();
                flag_release(&g_f_x[j]);
            }
        }
        return;
    }

    // =========================== layer blocks ===============================
    const int l = z - 1;
    const int n = l * M_ + m;
    const int b = jb + t * 2;                      // batch pair in tile j

    // ---- prologue ----------------------------------------------------------
    #pragma unroll
    for (int i = t; i < D_ * K_; i += 128) {
        int d = i >> 5, k = i & 31;
        sm.c.sWt[k * D_ + d] = W[(size_t)n * (D_ * K_) + i];
    }
    if (t < D_) sm.c.sBias[t] = bias[n * D_ + t];

    // ---- per-source-node dataflow wait (lane t owns gather t) -------------
    if (t < K_) {
        int sn = src_node[n * K_ + t];
        int sf = src_feat[n * K_ + t];
        unsigned off;
        const int* fp;
        if (sn == 0) {
            off = XT_OFF + (unsigned)sf * B_;
            fp  = &g_f_x[j];
        } else if (sn <= l * M_) {
            off = OUT_OFF + ((unsigned)(sn - 1) * D_ + (unsigned)sf) * B_;
            fp  = &g_f_out[j * N_ + (sn - 1)];
        } else {
            off = TR_OFF  + ((unsigned)(sn - 1) * D_ + (unsigned)sf) * B_;
            fp  = &g_f_tr[j * N_ + (sn - 1)];
        }
        sm.c.sOff[t] = off;
        flag_wait(fp);
    }
    __syncthreads();

    // ---- compute: fp32x2 d-pair core, 2 flights of 16 gathers --------------
    unsigned long long accx[D_ / 2], accy[D_ / 2];
    #pragma unroll
    for (int dp = 0; dp < D_ / 2; ++dp) {
        unsigned long long bp = pack2(sm.c.sBias[2 * dp], sm.c.sBias[2 * dp + 1]);
        accx[dp] = bp;
        accy[dp] = bp;
    }

    #pragma unroll
    for (int r = 0; r < 2; ++r) {
        float2 g[16];
        #pragma unroll
        for (int jj = 0; jj < 16; ++jj)
            g[jj] = *reinterpret_cast<const float2*>(
                &g_scratch[sm.c.sOff[16 * r + jj] + (unsigned)b]);

        #pragma unroll
        for (int jj = 0; jj < 16; ++jj) {
            const int k = 16 * r + jj;
            unsigned long long gx = pack2(g[jj].x, g[jj].x);
            unsigned long long gy = pack2(g[jj].y, g[jj].y);
            const ulonglong2* wrow =
                reinterpret_cast<const ulonglong2*>(&sm.c.sWt[k * D_]);
            #pragma unroll
            for (int q = 0; q < 4; ++q) {
                ulonglong2 w2 = wrow[q];
                accx[2 * q + 0] = fma2(gx, w2.x, accx[2 * q + 0]);
                accx[2 * q + 1] = fma2(gx, w2.y, accx[2 * q + 1]);
                accy[2 * q + 0] = fma2(gy, w2.x, accy[2 * q + 0]);
                accy[2 * q + 1] = fma2(gy, w2.y, accy[2 * q + 1]);
            }
        }
    }

    float ax[D_], ay[D_];
    #pragma unroll
    for (int dp = 0; dp < D_ / 2; ++dp) {
        float2 vx = unpack2(accx[dp]), vy = unpack2(accy[dp]);
        ax[2 * dp]     = fmaxf(vx.x, 0.0f);
        ax[2 * dp + 1] = fmaxf(vx.y, 0.0f);
        ay[2 * dp]     = fmaxf(vy.x, 0.0f);
        ay[2 * dp + 1] = fmaxf(vy.y, 0.0f);
    }

    // ---- outT store + early release signal (skip on last layer) -----------
    if (l != L_ - 1) {
        float* oT = g_scratch + OUT_OFF + (size_t)n * (D_ * B_);
        #pragma unroll
        for (int d = 0; d < D_; ++d)
            *reinterpret_cast<float2*>(&oT[d * B_ + b]) = make_float2(ax[d], ay[d]);
        __syncthreads();
        if (t == 0) {
            __threadfence();
            flag_release(&g_f_out[j * N_ + n]);
        }
    }

    // ---- final output (N, B, D) --------------------------------------------
    float* o = out + ((size_t)n * B_ + (size_t)b) * D_;
    #pragma unroll
    for (int d4 = 0; d4 < D_ / 4; ++d4) {
        *reinterpret_cast<float4*>(&o[4 * d4]) =
            make_float4(ax[4 * d4 + 0], ax[4 * d4 + 1], ax[4 * d4 + 2], ax[4 * d4 + 3]);
        *reinterpret_cast<float4*>(&o[D_ + 4 * d4]) =
            make_float4(ay[4 * d4 + 0], ay[4 * d4 + 1], ay[4 * d4 + 2], ay[4 * d4 + 3]);
    }
}

extern "C" void kernel_launch(void* const* d_in, const int* in_sizes, int n_in,
                              void* d_out, int out_size)
{
    const float* x      = (const float*)d_in[0];
    const float* trace  = (const float*)d_in[1];
    const int*   src_n  = (const int*)d_in[2];
    const int*   src_f  = (const int*)d_in[3];
    const float* W      = (const float*)d_in[4];
    const float* bias   = (const float*)d_in[5];
    float* out = (float*)d_out;

    zero_flags_kernel<<<(N_ * NT_ + 255) / 256, 256>>>();
    fused_all<<<dim3(M_, L_ + 1, NT_), 128>>>(out, x, trace, src_n, src_f, W, bias);
}

// round 15
// speedup vs baseline: 2.7198x; 2.7198x over previous
#include <cuda_runtime.h>
#include <cstdint>
#include <cstddef>

#define L_  8
#define M_  128
#define K_  32
#define D_  16
#define B_  2048
#define N_  1024   /* L_*M_ */
#define NT_ 8      /* batch tiles of 256 */
#define BT_ 256    /* batch-tile width */
#define TPAD 260   /* smem tile row pad (x4 -> 16B-aligned rows) */
#define TOT_ (L_ * M_)   /* layer blocks per tile */

#define XT_OFF   0u
#define TR_OFF   ((unsigned)(D_ * B_))
#define OUT_OFF  ((unsigned)(D_ * B_ + N_ * D_ * B_))

static __device__ float g_scratch[(size_t)D_ * B_ + 2ull * N_ * D_ * B_];
static __device__ int   g_f_tr[NT_ * N_];   // [j*N_+n] traceT row-slice ready
static __device__ int   g_f_out[NT_ * N_];  // [j*N_+n] outT row-slice ready
static __device__ int   g_f_x[NT_];         // xT slice ready
static __device__ int   g_done[NT_];        // finished layer blocks per tile

// ---- packed fp32x2 helpers (sm_10x) ---------------------------------------
__device__ __forceinline__ unsigned long long fma2(
    unsigned long long a, unsigned long long b, unsigned long long c)
{
    unsigned long long d;
    asm("fma.rn.f32x2 %0, %1, %2, %3;" : "=l"(d) : "l"(a), "l"(b), "l"(c));
    return d;
}
__device__ __forceinline__ unsigned long long pack2(float lo, float hi)
{
    unsigned long long r;
    asm("mov.b64 %0, {%1, %2};" : "=l"(r) : "f"(lo), "f"(hi));
    return r;
}
__device__ __forceinline__ float2 unpack2(unsigned long long v)
{
    float2 r;
    asm("mov.b64 {%0, %1}, %2;" : "=f"(r.x), "=f"(r.y) : "l"(v));
    return r;
}
__device__ __forceinline__ void flag_release(int* p)
{
    asm volatile("st.release.gpu.s32 [%0], %1;" :: "l"(p), "r"(1) : "memory");
}
__device__ __forceinline__ void flag_wait(const int* p)
{
    int v;
    for (;;) {
        asm volatile("ld.acquire.gpu.s32 %0, [%1];" : "=r"(v) : "l"(p) : "memory");
        if (v) break;
        __nanosleep(64);
    }
}

// ---------------------------------------------------------------------------
// Transpose one (BT_, D) contiguous slice -> 16 rows of BT_ floats.
// Source is streamed with evict-first (__ldcs): never re-read.
// ---------------------------------------------------------------------------
__device__ __forceinline__ void transpose_slice(
    float (*tile)[TPAD], const float* __restrict__ src, float* __restrict__ dst,
    int jb, int t)
{
    const float4* s4 = reinterpret_cast<const float4*>(src);
    #pragma unroll
    for (int i = t; i < (BT_ * D_) / 4; i += 128) {
        float4 v = __ldcs(&s4[i]);
        int bb = i >> 2;
        int d4 = (i & 3) * 4;
        tile[d4 + 0][bb] = v.x;
        tile[d4 + 1][bb] = v.y;
        tile[d4 + 2][bb] = v.z;
        tile[d4 + 3][bb] = v.w;
    }
    __syncthreads();
    #pragma unroll
    for (int i = t; i < (BT_ * D_) / 4; i += 128) {
        int d = i >> 6;
        int c = (i & 63) * 4;
        *reinterpret_cast<float4*>(&dst[(size_t)d * B_ + jb + c]) =
            *reinterpret_cast<const float4*>(&tile[d][c]);
    }
    __syncthreads();
}

// ---------------------------------------------------------------------------
// ONE kernel, LAYER-MAJOR bid order (R11):
//   grid = (M_, NT_, L_+1): z = 0 -> transpose; z = 1..8 -> layer z-1.
// Per-source-node dataflow flags; in-kernel flag reset (no prefix kernel).
// Core: 2 batches/thread, fp32x2 d-pair, 2 flights of 16 gathers.
// ---------------------------------------------------------------------------
__global__ void __launch_bounds__(128, 6) fused_all(
    float* __restrict__ out,
    const float* __restrict__ x,
    const float* __restrict__ trace,
    const int* __restrict__ src_node,
    const int* __restrict__ src_feat,
    const float* __restrict__ W,
    const float* __restrict__ bias)
{
    __shared__ union SM {
        float tile[D_][TPAD];                      // transpose staging
        struct {
            float    sWt[K_ * D_];
            float    sBias[D_];
            unsigned sOff[K_];
        } c;                                       // layer compute
    } sm;
    __shared__ int s_last;

    const int m  = blockIdx.x;
    const int j  = blockIdx.y;
    const int z  = blockIdx.z;
    const int t  = threadIdx.x;
    const int jb = j * BT_;

    // ======================= transpose blocks (z == 0) ======================
    if (z == 0) {
        #pragma unroll 1
        for (int i = 0; i < 8; ++i) {
            int n = m * 8 + i;
            transpose_slice(sm.tile,
                            trace + ((size_t)n * B_ + jb) * D_,
                            g_scratch + TR_OFF + (size_t)n * D_ * B_, jb, t);
            if (t == 0) {
                __threadfence();
                flag_release(&g_f_tr[j * N_ + n]);
            }
        }
        if (m == 0) {
            transpose_slice(sm.tile, x + (size_t)jb * D_,
                            g_scratch + XT_OFF, jb, t);
            if (t == 0) {
                __threadfence();
                flag_release(&g_f_x[j]);
            }
        }
        return;
    }

    // =========================== layer blocks ===============================
    const int l = z - 1;
    const int n = l * M_ + m;
    const int b = jb + t * 2;                      // batch pair in tile j

    // ---- prologue ----------------------------------------------------------
    #pragma unroll
    for (int i = t; i < D_ * K_; i += 128) {
        int d = i >> 5, k = i & 31;
        sm.c.sWt[k * D_ + d] = W[(size_t)n * (D_ * K_) + i];
    }
    if (t < D_) sm.c.sBias[t] = bias[n * D_ + t];

    // ---- per-source-node dataflow wait (lane t owns gather t) -------------
    if (t < K_) {
        int sn = src_node[n * K_ + t];
        int sf = src_feat[n * K_ + t];
        unsigned off;
        const int* fp;
        if (sn == 0) {
            off = XT_OFF + (unsigned)sf * B_;
            fp  = &g_f_x[j];
        } else if (sn <= l * M_) {
            off = OUT_OFF + ((unsigned)(sn - 1) * D_ + (unsigned)sf) * B_;
            fp  = &g_f_out[j * N_ + (sn - 1)];
        } else {
            off = TR_OFF  + ((unsigned)(sn - 1) * D_ + (unsigned)sf) * B_;
            fp  = &g_f_tr[j * N_ + (sn - 1)];
        }
        sm.c.sOff[t] = off;
        flag_wait(fp);
    }
    __syncthreads();

    // ---- compute: fp32x2 d-pair core, 2 flights of 16 gathers --------------
    unsigned long long accx[D_ / 2], accy[D_ / 2];
    #pragma unroll
    for (int dp = 0; dp < D_ / 2; ++dp) {
        unsigned long long bp = pack2(sm.c.sBias[2 * dp], sm.c.sBias[2 * dp + 1]);
        accx[dp] = bp;
        accy[dp] = bp;
    }

    #pragma unroll
    for (int r = 0; r < 2; ++r) {
        float2 g[16];
        #pragma unroll
        for (int jj = 0; jj < 16; ++jj)
            g[jj] = *reinterpret_cast<const float2*>(
                &g_scratch[sm.c.sOff[16 * r + jj] + (unsigned)b]);

        #pragma unroll
        for (int jj = 0; jj < 16; ++jj) {
            const int k = 16 * r + jj;
            unsigned long long gx = pack2(g[jj].x, g[jj].x);
            unsigned long long gy = pack2(g[jj].y, g[jj].y);
            const ulonglong2* wrow =
                reinterpret_cast<const ulonglong2*>(&sm.c.sWt[k * D_]);
            #pragma unroll
            for (int q = 0; q < 4; ++q) {
                ulonglong2 w2 = wrow[q];
                accx[2 * q + 0] = fma2(gx, w2.x, accx[2 * q + 0]);
                accx[2 * q + 1] = fma2(gx, w2.y, accx[2 * q + 1]);
                accy[2 * q + 0] = fma2(gy, w2.x, accy[2 * q + 0]);
                accy[2 * q + 1] = fma2(gy, w2.y, accy[2 * q + 1]);
            }
        }
    }

    float ax[D_], ay[D_];
    #pragma unroll
    for (int dp = 0; dp < D_ / 2; ++dp) {
        float2 vx = unpack2(accx[dp]), vy = unpack2(accy[dp]);
        ax[2 * dp]     = fmaxf(vx.x, 0.0f);
        ax[2 * dp + 1] = fmaxf(vx.y, 0.0f);
        ay[2 * dp]     = fmaxf(vy.x, 0.0f);
        ay[2 * dp + 1] = fmaxf(vy.y, 0.0f);
    }

    // ---- outT store + early release signal (skip on last layer) -----------
    if (l != L_ - 1) {
        float* oT = g_scratch + OUT_OFF + (size_t)n * (D_ * B_);
        #pragma unroll
        for (int d = 0; d < D_; ++d)
            *reinterpret_cast<float2*>(&oT[d * B_ + b]) = make_float2(ax[d], ay[d]);
        __syncthreads();
        if (t == 0) {
            __threadfence();
            flag_release(&g_f_out[j * N_ + n]);
        }
    }

    // ---- final output (N, B, D): streaming stores (never re-read) ---------
    float* o = out + ((size_t)n * B_ + (size_t)b) * D_;
    #pragma unroll
    for (int d4 = 0; d4 < D_ / 4; ++d4) {
        __stcs(reinterpret_cast<float4*>(&o[4 * d4]),
               make_float4(ax[4 * d4 + 0], ax[4 * d4 + 1],
                           ax[4 * d4 + 2], ax[4 * d4 + 3]));
        __stcs(reinterpret_cast<float4*>(&o[D_ + 4 * d4]),
               make_float4(ay[4 * d4 + 0], ay[4 * d4 + 1],
                           ay[4 * d4 + 2], ay[4 * d4 + 3]));
    }

    // ---- in-kernel flag reset: last finishing layer block of tile j -------
    // All 1024 layer blocks of tile j have passed their flag reads before
    // the counter reaches TOT_, so zeroing here is race-free; the kernel
    // boundary orders it before the next graph replay.
    __syncthreads();
    if (t == 0)
        s_last = (atomicAdd(&g_done[j], 1) == TOT_ - 1) ? 1 : 0;
    __syncthreads();
    if (s_last) {
        #pragma unroll 4
        for (int i = t; i < N_; i += 128) {
            g_f_tr[j * N_ + i]  = 0;
            g_f_out[j * N_ + i] = 0;
        }
        if (t == 0) { g_f_x[j] = 0; g_done[j] = 0; }
    }
}

extern "C" void kernel_launch(void* const* d_in, const int* in_sizes, int n_in,
                              void* d_out, int out_size)
{
    const float* x      = (const float*)d_in[0];
    const float* trace  = (const float*)d_in[1];
    const int*   src_n  = (const int*)d_in[2];
    const int*   src_f  = (const int*)d_in[3];
    const float* W      = (const float*)d_in[4];
    const float* bias   = (const float*)d_in[5];
    float* out = (float*)d_out;

    fused_all<<<dim3(M_, NT_, L_ + 1), 128>>>(out, x, trace, src_n, src_f, W, bias);
}

// round 16
// speedup vs baseline: 2.8581x; 1.0508x over previous
#include <cuda_runtime.h>
#include <cstdint>
#include <cstddef>

#define L_  8
#define M_  128
#define K_  32
#define D_  16
#define B_  2048
#define N_  1024   /* L_*M_ */
#define NT_ 8      /* batch tiles of 256 */
#define BT_ 256    /* batch-tile width */
#define TPAD 260   /* smem tile row pad (x4 -> 16B-aligned rows) */

#define XT_OFF   0u
#define TR_OFF   ((unsigned)(D_ * B_))
#define OUT_OFF  ((unsigned)(D_ * B_ + N_ * D_ * B_))

static __device__ float g_scratch[(size_t)D_ * B_ + 2ull * N_ * D_ * B_];
static __device__ int   g_f_tr[NT_ * N_];   // [j*N_+n] traceT row-slice ready
static __device__ int   g_f_out[NT_ * N_];  // [j*N_+n] outT row-slice ready
static __device__ int   g_f_x[NT_];         // xT slice ready

// ---- packed fp32x2 helpers (sm_10x) ---------------------------------------
__device__ __forceinline__ unsigned long long fma2(
    unsigned long long a, unsigned long long b, unsigned long long c)
{
    unsigned long long d;
    asm("fma.rn.f32x2 %0, %1, %2, %3;" : "=l"(d) : "l"(a), "l"(b), "l"(c));
    return d;
}
__device__ __forceinline__ unsigned long long pack2(float lo, float hi)
{
    unsigned long long r;
    asm("mov.b64 %0, {%1, %2};" : "=l"(r) : "f"(lo), "f"(hi));
    return r;
}
__device__ __forceinline__ float2 unpack2(unsigned long long v)
{
    float2 r;
    asm("mov.b64 {%0, %1}, %2;" : "=f"(r.x), "=f"(r.y) : "l"(v));
    return r;
}
// Release store: all prior writes of the BLOCK are ordered before this store
// because it executes after bar.sync (a synchronizing op in the PTX model).
// No __threadfence (CCTL.IVALL / L1 flush) needed.
__device__ __forceinline__ void flag_release(int* p)
{
    asm volatile("st.release.gpu.s32 [%0], %1;" :: "l"(p), "r"(1) : "memory");
}
__device__ __forceinline__ void flag_wait(const int* p)
{
    int v;
    for (;;) {
        asm volatile("ld.acquire.gpu.s32 %0, [%1];" : "=r"(v) : "l"(p) : "memory");
        if (v) break;
        __nanosleep(64);
    }
}

// ---------------------------------------------------------------------------
// Zero the ready flags (must run before fused kernel each replay).
// ---------------------------------------------------------------------------
__global__ void zero_flags_kernel()
{
    int i = blockIdx.x * 256 + threadIdx.x;
    if (i < N_ * NT_) { g_f_tr[i] = 0; g_f_out[i] = 0; }
    if (i < NT_) g_f_x[i] = 0;
}

// ---------------------------------------------------------------------------
// Transpose one (BT_, D) contiguous slice -> 16 rows of BT_ floats.
// Ends with __syncthreads, so a following st.release by t0 covers all STGs.
// ---------------------------------------------------------------------------
__device__ __forceinline__ void transpose_slice(
    float (*tile)[TPAD], const float* __restrict__ src, float* __restrict__ dst,
    int jb, int t)
{
    const float4* s4 = reinterpret_cast<const float4*>(src);
    #pragma unroll
    for (int i = t; i < (BT_ * D_) / 4; i += 128) {
        float4 v = s4[i];
        int bb = i >> 2;
        int d4 = (i & 3) * 4;
        tile[d4 + 0][bb] = v.x;
        tile[d4 + 1][bb] = v.y;
        tile[d4 + 2][bb] = v.z;
        tile[d4 + 3][bb] = v.w;
    }
    __syncthreads();
    #pragma unroll
    for (int i = t; i < (BT_ * D_) / 4; i += 128) {
        int d = i >> 6;
        int c = (i & 63) * 4;
        *reinterpret_cast<float4*>(&dst[(size_t)d * B_ + jb + c]) =
            *reinterpret_cast<const float4*>(&tile[d][c]);
    }
    __syncthreads();
}

// ---------------------------------------------------------------------------
// ONE kernel, LAYER-MAJOR bid order:
//   grid = (M_, NT_, L_+1): z = 0 -> transpose; z = 1..8 -> layer z-1.
// Per-source-node dataflow flags (bar.sync + st.release / ld.acquire).
// Core: 2 batches/thread, fp32x2 d-pair, 2 flights of 16 gathers.
// ---------------------------------------------------------------------------
__global__ void __launch_bounds__(128, 6) fused_all(
    float* __restrict__ out,
    const float* __restrict__ x,
    const float* __restrict__ trace,
    const int* __restrict__ src_node,
    const int* __restrict__ src_feat,
    const float* __restrict__ W,
    const float* __restrict__ bias)
{
    __shared__ union SM {
        float tile[D_][TPAD];                      // transpose staging
        struct {
            float    sWt[K_ * D_];
            float    sBias[D_];
            unsigned sOff[K_];
        } c;                                       // layer compute
    } sm;

    const int m  = blockIdx.x;
    const int j  = blockIdx.y;
    const int z  = blockIdx.z;
    const int t  = threadIdx.x;
    const int jb = j * BT_;

    // ======================= transpose blocks (z == 0) ======================
    if (z == 0) {
        #pragma unroll 1
        for (int i = 0; i < 8; ++i) {
            int n = m * 8 + i;
            transpose_slice(sm.tile,
                            trace + ((size_t)n * B_ + jb) * D_,
                            g_scratch + TR_OFF + (size_t)n * D_ * B_, jb, t);
            if (t == 0)
                flag_release(&g_f_tr[j * N_ + n]);
        }
        if (m == 0) {
            transpose_slice(sm.tile, x + (size_t)jb * D_,
                            g_scratch + XT_OFF, jb, t);
            if (t == 0)
                flag_release(&g_f_x[j]);
        }
        return;
    }

    // =========================== layer blocks ===============================
    const int l = z - 1;
    const int n = l * M_ + m;
    const int b = jb + t * 2;                      // batch pair in tile j

    // ---- prologue ----------------------------------------------------------
    #pragma unroll
    for (int i = t; i < D_ * K_; i += 128) {
        int d = i >> 5, k = i & 31;
        sm.c.sWt[k * D_ + d] = W[(size_t)n * (D_ * K_) + i];
    }
    if (t < D_) sm.c.sBias[t] = bias[n * D_ + t];

    // ---- per-source-node dataflow wait (lane t owns gather t) -------------
    if (t < K_) {
        int sn = src_node[n * K_ + t];
        int sf = src_feat[n * K_ + t];
        unsigned off;
        const int* fp;
        if (sn == 0) {
            off = XT_OFF + (unsigned)sf * B_;
            fp  = &g_f_x[j];
        } else if (sn <= l * M_) {
            off = OUT_OFF + ((unsigned)(sn - 1) * D_ + (unsigned)sf) * B_;
            fp  = &g_f_out[j * N_ + (sn - 1)];
        } else {
            off = TR_OFF  + ((unsigned)(sn - 1) * D_ + (unsigned)sf) * B_;
            fp  = &g_f_tr[j * N_ + (sn - 1)];
        }
        sm.c.sOff[t] = off;
        flag_wait(fp);
    }
    __syncthreads();

    // ---- compute: fp32x2 d-pair core, 2 flights of 16 gathers --------------
    unsigned long long accx[D_ / 2], accy[D_ / 2];
    #pragma unroll
    for (int dp = 0; dp < D_ / 2; ++dp) {
        unsigned long long bp = pack2(sm.c.sBias[2 * dp], sm.c.sBias[2 * dp + 1]);
        accx[dp] = bp;
        accy[dp] = bp;
    }

    #pragma unroll
    for (int r = 0; r < 2; ++r) {
        float2 g[16];
        #pragma unroll
        for (int jj = 0; jj < 16; ++jj)
            g[jj] = *reinterpret_cast<const float2*>(
                &g_scratch[sm.c.sOff[16 * r + jj] + (unsigned)b]);

        #pragma unroll
        for (int jj = 0; jj < 16; ++jj) {
            const int k = 16 * r + jj;
            unsigned long long gx = pack2(g[jj].x, g[jj].x);
            unsigned long long gy = pack2(g[jj].y, g[jj].y);
            const ulonglong2* wrow =
                reinterpret_cast<const ulonglong2*>(&sm.c.sWt[k * D_]);
            #pragma unroll
            for (int q = 0; q < 4; ++q) {
                ulonglong2 w2 = wrow[q];
                accx[2 * q + 0] = fma2(gx, w2.x, accx[2 * q + 0]);
                accx[2 * q + 1] = fma2(gx, w2.y, accx[2 * q + 1]);
                accy[2 * q + 0] = fma2(gy, w2.x, accy[2 * q + 0]);
                accy[2 * q + 1] = fma2(gy, w2.y, accy[2 * q + 1]);
            }
        }
    }

    float ax[D_], ay[D_];
    #pragma unroll
    for (int dp = 0; dp < D_ / 2; ++dp) {
        float2 vx = unpack2(accx[dp]), vy = unpack2(accy[dp]);
        ax[2 * dp]     = fmaxf(vx.x, 0.0f);
        ax[2 * dp + 1] = fmaxf(vx.y, 0.0f);
        ay[2 * dp]     = fmaxf(vy.x, 0.0f);
        ay[2 * dp + 1] = fmaxf(vy.y, 0.0f);
    }

    // ---- outT store + release signal (skip on last layer) -----------------
    if (l != L_ - 1) {
        float* oT = g_scratch + OUT_OFF + (size_t)n * (D_ * B_);
        #pragma unroll
        for (int d = 0; d < D_; ++d)
            *reinterpret_cast<float2*>(&oT[d * B_ + b]) = make_float2(ax[d], ay[d]);
        __syncthreads();                 // all threads' oT stores ordered
        if (t == 0)
            flag_release(&g_f_out[j * N_ + n]);
    }

    // ---- final output (N, B, D) --------------------------------------------
    float* o = out + ((size_t)n * B_ + (size_t)b) * D_;
    #pragma unroll
    for (int d4 = 0; d4 < D_ / 4; ++d4) {
        *reinterpret_cast<float4*>(&o[4 * d4]) =
            make_float4(ax[4 * d4 + 0], ax[4 * d4 + 1], ax[4 * d4 + 2], ax[4 * d4 + 3]);
        *reinterpret_cast<float4*>(&o[D_ + 4 * d4]) =
            make_float4(ay[4 * d4 + 0], ay[4 * d4 + 1], ay[4 * d4 + 2], ay[4 * d4 + 3]);
    }
}

extern "C" void kernel_launch(void* const* d_in, const int* in_sizes, int n_in,
                              void* d_out, int out_size)
{
    const float* x      = (const float*)d_in[0];
    const float* trace  = (const float*)d_in[1];
    const int*   src_n  = (const int*)d_in[2];
    const int*   src_f  = (const int*)d_in[3];
    const float* W      = (const float*)d_in[4];
    const float* bias   = (const float*)d_in[5];
    float* out = (float*)d_out;

    zero_flags_kernel<<<(N_ * NT_ + 255) / 256, 256>>>();
    fused_all<<<dim3(M_, NT_, L_ + 1), 128>>>(out, x, trace, src_n, src_f, W, bias);
}

// round 17
// speedup vs baseline: 3.1200x; 1.0916x over previous
#include <cuda_runtime.h>
#include <cstdint>
#include <cstddef>

#define L_  8
#define M_  128
#define K_  32
#define D_  16
#define B_  2048
#define N_  1024   /* L_*M_ */
#define NT_ 8      /* batch tiles of 256 */
#define BT_ 256    /* batch-tile width */
#define TPAD 260   /* smem tile row pad (x4 -> 16B-aligned rows) */

#define XT_OFF   0u
#define TR_OFF   ((unsigned)(D_ * B_))
#define OUT_OFF  ((unsigned)(D_ * B_ + N_ * D_ * B_))

static __device__ float g_scratch[(size_t)D_ * B_ + 2ull * N_ * D_ * B_];
static __device__ int   g_f_tr[NT_ * N_];   // [j*N_+n] traceT row-slice ready
static __device__ int   g_f_out[NT_ * N_];  // [j*N_+n] outT row-slice ready
static __device__ int   g_f_x[NT_];         // xT slice ready

// ---- packed fp32x2 helpers (sm_10x) ---------------------------------------
__device__ __forceinline__ unsigned long long fma2(
    unsigned long long a, unsigned long long b, unsigned long long c)
{
    unsigned long long d;
    asm("fma.rn.f32x2 %0, %1, %2, %3;" : "=l"(d) : "l"(a), "l"(b), "l"(c));
    return d;
}
__device__ __forceinline__ unsigned long long pack2(float lo, float hi)
{
    unsigned long long r;
    asm("mov.b64 %0, {%1, %2};" : "=l"(r) : "f"(lo), "f"(hi));
    return r;
}
__device__ __forceinline__ float2 unpack2(unsigned long long v)
{
    float2 r;
    asm("mov.b64 {%0, %1}, %2;" : "=f"(r.x), "=f"(r.y) : "l"(v));
    return r;
}
// Release store after bar.sync: orders the whole block's prior writes
// (PTX memory model); no CCTL.IVALL-emitting __threadfence needed.
__device__ __forceinline__ void flag_release(int* p)
{
    asm volatile("st.release.gpu.s32 [%0], %1;" :: "l"(p), "r"(1) : "memory");
}
__device__ __forceinline__ void flag_wait(const int* p)
{
    int v;
    for (;;) {
        asm volatile("ld.acquire.gpu.s32 %0, [%1];" : "=r"(v) : "l"(p) : "memory");
        if (v) break;
        __nanosleep(64);
    }
}

// ---------------------------------------------------------------------------
// Zero the ready flags (must run before fused kernel each replay).
// ---------------------------------------------------------------------------
__global__ void zero_flags_kernel()
{
    int i = blockIdx.x * 256 + threadIdx.x;
    if (i < N_ * NT_) { g_f_tr[i] = 0; g_f_out[i] = 0; }
    if (i < NT_) g_f_x[i] = 0;
}

// ---------------------------------------------------------------------------
// Transpose one (BT_, D) contiguous slice -> 16 rows of BT_ floats.
// Ends with __syncthreads, so a following st.release by t0 covers all STGs.
// ---------------------------------------------------------------------------
__device__ __forceinline__ void transpose_slice(
    float (*tile)[TPAD], const float* __restrict__ src, float* __restrict__ dst,
    int jb, int t)
{
    const float4* s4 = reinterpret_cast<const float4*>(src);
    #pragma unroll
    for (int i = t; i < (BT_ * D_) / 4; i += 128) {
        float4 v = s4[i];
        int bb = i >> 2;
        int d4 = (i & 3) * 4;
        tile[d4 + 0][bb] = v.x;
        tile[d4 + 1][bb] = v.y;
        tile[d4 + 2][bb] = v.z;
        tile[d4 + 3][bb] = v.w;
    }
    __syncthreads();
    #pragma unroll
    for (int i = t; i < (BT_ * D_) / 4; i += 128) {
        int d = i >> 6;
        int c = (i & 63) * 4;
        *reinterpret_cast<float4*>(&dst[(size_t)d * B_ + jb + c]) =
            *reinterpret_cast<const float4*>(&tile[d][c]);
    }
    __syncthreads();
}

// ---------------------------------------------------------------------------
// ONE kernel, LAYER-MAJOR bid order, fine-grained transpose:
//   grid = (M_, NT_, 16): z in [0,8)  -> transpose ONE node slice
//                                        (n = z*M_ + m) of tile j;
//                         z in [8,16) -> layer z-8.
// Per-source-node dataflow flags (bar.sync + st.release / ld.acquire).
// Core: 2 batches/thread, fp32x2 d-pair, 2 flights of 16 gathers.
// ---------------------------------------------------------------------------
__global__ void __launch_bounds__(128, 6) fused_all(
    float* __restrict__ out,
    const float* __restrict__ x,
    const float* __restrict__ trace,
    const int* __restrict__ src_node,
    const int* __restrict__ src_feat,
    const float* __restrict__ W,
    const float* __restrict__ bias)
{
    __shared__ union SM {
        float tile[D_][TPAD];                      // transpose staging
        struct {
            float    sWt[K_ * D_];
            float    sBias[D_];
            unsigned sOff[K_];
        } c;                                       // layer compute
    } sm;

    const int m  = blockIdx.x;
    const int j  = blockIdx.y;
    const int z  = blockIdx.z;
    const int t  = threadIdx.x;
    const int jb = j * BT_;

    // ======================= transpose blocks (z < 8) =======================
    if (z < 8) {
        if (z == 0 && m == 0) {                    // earliest-bid block: x first
            transpose_slice(sm.tile, x + (size_t)jb * D_,
                            g_scratch + XT_OFF, jb, t);
            if (t == 0)
                flag_release(&g_f_x[j]);
        }
        const int n = z * M_ + m;
        transpose_slice(sm.tile,
                        trace + ((size_t)n * B_ + jb) * D_,
                        g_scratch + TR_OFF + (size_t)n * D_ * B_, jb, t);
        if (t == 0)
            flag_release(&g_f_tr[j * N_ + n]);
        return;
    }

    // =========================== layer blocks ===============================
    const int l = z - 8;
    const int n = l * M_ + m;
    const int b = jb + t * 2;                      // batch pair in tile j

    // ---- prologue ----------------------------------------------------------
    #pragma unroll
    for (int i = t; i < D_ * K_; i += 128) {
        int d = i >> 5, k = i & 31;
        sm.c.sWt[k * D_ + d] = W[(size_t)n * (D_ * K_) + i];
    }
    if (t < D_) sm.c.sBias[t] = bias[n * D_ + t];

    // ---- per-source-node dataflow wait (lane t owns gather t) -------------
    if (t < K_) {
        int sn = src_node[n * K_ + t];
        int sf = src_feat[n * K_ + t];
        unsigned off;
        const int* fp;
        if (sn == 0) {
            off = XT_OFF + (unsigned)sf * B_;
            fp  = &g_f_x[j];
        } else if (sn <= l * M_) {
            off = OUT_OFF + ((unsigned)(sn - 1) * D_ + (unsigned)sf) * B_;
            fp  = &g_f_out[j * N_ + (sn - 1)];
        } else {
            off = TR_OFF  + ((unsigned)(sn - 1) * D_ + (unsigned)sf) * B_;
            fp  = &g_f_tr[j * N_ + (sn - 1)];
        }
        sm.c.sOff[t] = off;
        flag_wait(fp);
    }
    __syncthreads();

    // ---- compute: fp32x2 d-pair core, 2 flights of 16 gathers --------------
    unsigned long long accx[D_ / 2], accy[D_ / 2];
    #pragma unroll
    for (int dp = 0; dp < D_ / 2; ++dp) {
        unsigned long long bp = pack2(sm.c.sBias[2 * dp], sm.c.sBias[2 * dp + 1]);
        accx[dp] = bp;
        accy[dp] = bp;
    }

    #pragma unroll
    for (int r = 0; r < 2; ++r) {
        float2 g[16];
        #pragma unroll
        for (int jj = 0; jj < 16; ++jj)
            g[jj] = *reinterpret_cast<const float2*>(
                &g_scratch[sm.c.sOff[16 * r + jj] + (unsigned)b]);

        #pragma unroll
        for (int jj = 0; jj < 16; ++jj) {
            const int k = 16 * r + jj;
            unsigned long long gx = pack2(g[jj].x, g[jj].x);
            unsigned long long gy = pack2(g[jj].y, g[jj].y);
            const ulonglong2* wrow =
                reinterpret_cast<const ulonglong2*>(&sm.c.sWt[k * D_]);
            #pragma unroll
            for (int q = 0; q < 4; ++q) {
                ulonglong2 w2 = wrow[q];
                accx[2 * q + 0] = fma2(gx, w2.x, accx[2 * q + 0]);
                accx[2 * q + 1] = fma2(gx, w2.y, accx[2 * q + 1]);
                accy[2 * q + 0] = fma2(gy, w2.x, accy[2 * q + 0]);
                accy[2 * q + 1] = fma2(gy, w2.y, accy[2 * q + 1]);
            }
        }
    }

    float ax[D_], ay[D_];
    #pragma unroll
    for (int dp = 0; dp < D_ / 2; ++dp) {
        float2 vx = unpack2(accx[dp]), vy = unpack2(accy[dp]);
        ax[2 * dp]     = fmaxf(vx.x, 0.0f);
        ax[2 * dp + 1] = fmaxf(vx.y, 0.0f);
        ay[2 * dp]     = fmaxf(vy.x, 0.0f);
        ay[2 * dp + 1] = fmaxf(vy.y, 0.0f);
    }

    // ---- outT store + release signal (skip on last layer) -----------------
    if (l != L_ - 1) {
        float* oT = g_scratch + OUT_OFF + (size_t)n * (D_ * B_);
        #pragma unroll
        for (int d = 0; d < D_; ++d)
            *reinterpret_cast<float2*>(&oT[d * B_ + b]) = make_float2(ax[d], ay[d]);
        __syncthreads();                 // all threads' oT stores ordered
        if (t == 0)
            flag_release(&g_f_out[j * N_ + n]);
    }

    // ---- final output (N, B, D) --------------------------------------------
    float* o = out + ((size_t)n * B_ + (size_t)b) * D_;
    #pragma unroll
    for (int d4 = 0; d4 < D_ / 4; ++d4) {
        *reinterpret_cast<float4*>(&o[4 * d4]) =
            make_float4(ax[4 * d4 + 0], ax[4 * d4 + 1], ax[4 * d4 + 2], ax[4 * d4 + 3]);
        *reinterpret_cast<float4*>(&o[D_ + 4 * d4]) =
            make_float4(ay[4 * d4 + 0], ay[4 * d4 + 1], ay[4 * d4 + 2], ay[4 * d4 + 3]);
    }
}

extern "C" void kernel_launch(void* const* d_in, const int* in_sizes, int n_in,
                              void* d_out, int out_size)
{
    const float* x      = (const float*)d_in[0];
    const float* trace  = (const float*)d_in[1];
    const int*   src_n  = (const int*)d_in[2];
    const int*   src_f  = (const int*)d_in[3];
    const float* W      = (const float*)d_in[4];
    const float* bias   = (const float*)d_in[5];
    float* out = (float*)d_out;

    zero_flags_kernel<<<(N_ * NT_ + 255) / 256, 256>>>();
    fused_all<<<dim3(M_, NT_, 16), 128>>>(out, x, trace, src_n, src_f, W, bias);
}